// round 14
// baseline (speedup 1.0000x reference)
#include <cuda_runtime.h>
#include <cuda_fp16.h>
#include <cstdint>

#define N_NODES 50000
#define N_EDGES 800000
#define EDGE_F  96
#define NODE_F  256
#define GLOB_F  64
#define HIDDEN  1024
#define N_GRAPHS 8
#define K1PAD   544              // x|sum|max|mean = 544 = 17*32
#define MTILES  391
#define MPAD    (MTILES*128)     // 50048

// ---------------- device scratch (allocation-free per harness rules) -------
__device__ int   g_cnt[N_NODES];                   // counts, then fill-cursor
__device__ int   g_start[N_NODES + 1];             // CSR offsets (+sentinel)
__device__ int   g_eidx[N_EDGES];
__device__ float g_ub[N_GRAPHS * HIDDEN];          // b1 + u[g] @ W1u
__device__ __half g_A [(size_t)MPAD*K1PAD];        // fp16 MLP input
__device__ __half g_H [(size_t)MPAD*HIDDEN];       // fp16 hidden acts
__device__ __half g_B1[(size_t)HIDDEN*K1PAD];      // W1^T fp16
__device__ __half g_B2[(size_t)NODE_F*HIDDEN];     // W2^T fp16

// ---------------- PTX helpers ----------------------------------------------
__device__ __forceinline__ uint32_t smem_u32(const void* p) {
    uint32_t a;
    asm("{ .reg .u64 t; cvta.to.shared.u64 t, %1; cvt.u32.u64 %0, t; }" : "=r"(a) : "l"(p));
    return a;
}
#define CPASYNC16(s,g) asm volatile("cp.async.cg.shared.global [%0], [%1], 16;" :: "r"(s), "l"(g))
#define CPCOMMIT()     asm volatile("cp.async.commit_group;" ::: "memory")
#define CPWAIT2()      asm volatile("cp.async.wait_group 2;" ::: "memory")

#define LDSM4(r0,r1,r2,r3,addr) \
    asm volatile("ldmatrix.sync.aligned.m8n8.x4.shared.b16 {%0,%1,%2,%3}, [%4];" \
        : "=r"(r0),"=r"(r1),"=r"(r2),"=r"(r3) : "r"(addr))

#define MMA16816(d,a,b0,b1) \
    asm volatile("mma.sync.aligned.m16n8k16.row.col.f32.f16.f16.f32 " \
        "{%0,%1,%2,%3}, {%4,%5,%6,%7}, {%8,%9}, {%0,%1,%2,%3};" \
        : "+f"((d)[0]),"+f"((d)[1]),"+f"((d)[2]),"+f"((d)[3]) \
        : "r"((a)[0]),"r"((a)[1]),"r"((a)[2]),"r"((a)[3]), "r"(b0),"r"(b1))

__device__ __forceinline__ uint32_t pk_h(float a, float b) {
    __half2 h = __floats2half2_rn(a, b);
    return *(uint32_t*)&h;
}

// ---------------- phase 1: CSR build + fused gather/compose ------------------
__global__ void zero_counts() {
    int i = blockIdx.x * blockDim.x + threadIdx.x;
    if (i < N_NODES) g_cnt[i] = 0;
}
__global__ void count_kernel(const int* __restrict__ dst) {
    int i = blockIdx.x * blockDim.x + threadIdx.x;
    if (i < N_EDGES) atomicAdd(&g_cnt[dst[i]], 1);
}
// single block, 1024 threads; warp-shuffle scan
__global__ void scan_kernel() {
    __shared__ int wsum[32];
    __shared__ int carry;
    int tid = threadIdx.x;
    int lane = tid & 31, warp = tid >> 5;
    if (tid == 0) carry = 0;
    __syncthreads();
    for (int base = 0; base < N_NODES; base += 1024) {
        int i = base + tid;
        int v = (i < N_NODES) ? g_cnt[i] : 0;
        int inc = v;
#pragma unroll
        for (int off = 1; off < 32; off <<= 1) {
            int t = __shfl_up_sync(0xffffffff, inc, off);
            if (lane >= off) inc += t;
        }
        if (lane == 31) wsum[warp] = inc;
        __syncthreads();
        if (warp == 0) {
            int w = wsum[lane];
#pragma unroll
            for (int off = 1; off < 32; off <<= 1) {
                int t = __shfl_up_sync(0xffffffff, w, off);
                if (lane >= off) w += t;
            }
            wsum[lane] = w;
        }
        __syncthreads();
        int excl = inc - v + (warp > 0 ? wsum[warp - 1] : 0) + carry;
        if (i < N_NODES) {
            g_start[i] = excl;
            g_cnt[i] = 0;                       // reset: becomes fill cursor
        }
        __syncthreads();
        if (tid == 1023) carry = excl + v;
        __syncthreads();
    }
    if (tid == 0) g_start[N_NODES] = N_EDGES;   // sentinel
}
__global__ void fill_kernel(const int* __restrict__ dst) {
    int i = blockIdx.x * blockDim.x + threadIdx.x;
    if (i >= N_EDGES) return;
    int c = dst[i];
    int p = atomicAdd(&g_cnt[c], 1);
    g_eidx[g_start[c] + p] = i;
}
// warp per node; lanes 0-23 own float4 feature chunks {4l..4l+3}.
// Unrolled x4 -> up to 96 independent 16B loads in flight per warp.
__global__ void gather_kernel(const float* __restrict__ ea, const float* __restrict__ x) {
    int w = (blockIdx.x * blockDim.x + threadIdx.x) >> 5;
    int lid = threadIdx.x & 31;
    if (w >= N_NODES) return;
    int s = g_start[w], d = g_start[w + 1] - s;
    float ninf = __int_as_float(0xff800000);
    float4 sum = make_float4(0.f, 0.f, 0.f, 0.f);
    float4 mx  = make_float4(ninf, ninf, ninf, ninf);
    if (lid < 24) {
        int j = 0;
        for (; j + 4 <= d; j += 4) {
            const float4* r0 = (const float4*)(ea + (size_t)g_eidx[s + j]     * EDGE_F) + lid;
            const float4* r1 = (const float4*)(ea + (size_t)g_eidx[s + j + 1] * EDGE_F) + lid;
            const float4* r2 = (const float4*)(ea + (size_t)g_eidx[s + j + 2] * EDGE_F) + lid;
            const float4* r3 = (const float4*)(ea + (size_t)g_eidx[s + j + 3] * EDGE_F) + lid;
            float4 a = *r0, b = *r1, c = *r2, e = *r3;
            sum.x += a.x + b.x + c.x + e.x;
            sum.y += a.y + b.y + c.y + e.y;
            sum.z += a.z + b.z + c.z + e.z;
            sum.w += a.w + b.w + c.w + e.w;
            mx.x = fmaxf(fmaxf(fmaxf(mx.x, a.x), fmaxf(b.x, c.x)), e.x);
            mx.y = fmaxf(fmaxf(fmaxf(mx.y, a.y), fmaxf(b.y, c.y)), e.y);
            mx.z = fmaxf(fmaxf(fmaxf(mx.z, a.z), fmaxf(b.z, c.z)), e.z);
            mx.w = fmaxf(fmaxf(fmaxf(mx.w, a.w), fmaxf(b.w, c.w)), e.w);
        }
        for (; j < d; ++j) {
            float4 a = *((const float4*)(ea + (size_t)g_eidx[s + j] * EDGE_F) + lid);
            sum.x += a.x; sum.y += a.y; sum.z += a.z; sum.w += a.w;
            mx.x = fmaxf(mx.x, a.x); mx.y = fmaxf(mx.y, a.y);
            mx.z = fmaxf(mx.z, a.z); mx.w = fmaxf(mx.w, a.w);
        }
    }
    if (d == 0) mx = make_float4(0.f, 0.f, 0.f, 0.f);
    float inv = d > 0 ? 1.f / (float)d : 0.f;

    __half* A = g_A + (size_t)w * K1PAD;
    if (lid < 24) {
        int c0 = 4 * lid;
        *(uint2*)(A + 256 + c0) = make_uint2(pk_h(sum.x, sum.y), pk_h(sum.z, sum.w));
        *(uint2*)(A + 352 + c0) = make_uint2(pk_h(mx.x, mx.y),  pk_h(mx.z, mx.w));
        *(uint2*)(A + 448 + c0) = make_uint2(pk_h(sum.x * inv, sum.y * inv),
                                             pk_h(sum.z * inv, sum.w * inv));
    }
    const float4* xr = (const float4*)(x + (size_t)w * NODE_F);
#pragma unroll
    for (int t = 0; t < 2; ++t) {
        int c4 = t * 32 + lid;                  // float4 index 0..63
        float4 v = xr[c4];
        *(uint2*)(A + 4 * c4) = make_uint2(pk_h(v.x, v.y), pk_h(v.z, v.w));
    }
}
// zero the padding rows [N_NODES, MPAD)
__global__ void pad_rows() {
    int i = blockIdx.x * blockDim.x + threadIdx.x;   // (MPAD-N_NODES)*136 uint2
    if (i >= (MPAD - N_NODES) * 136) return;
    int n = N_NODES + i / 136, q = i - (i / 136) * 136;
    *(uint2*)(g_A + (size_t)n * K1PAD + 4 * q) = make_uint2(0u, 0u);
}

// u-bias table: ub[g][n] = b1[n] + sum_k u[g][k] * W1[544+k][n]
__global__ void ub_kernel(const float* __restrict__ u, const float* __restrict__ W1,
                          const float* __restrict__ b1) {
    int i = blockIdx.x * blockDim.x + threadIdx.x;
    if (i >= N_GRAPHS * HIDDEN) return;
    int g = i / HIDDEN, n = i - g * HIDDEN;
    float acc = b1[n];
#pragma unroll 8
    for (int k = 0; k < GLOB_F; ++k)
        acc += u[(size_t)g * GLOB_F + k] * W1[(size_t)(544 + k) * HIDDEN + n];
    g_ub[i] = acc;
}

// coalesced 32x32 smem-tile transpose + fp16 convert of W1 (k<544) and W2.
__global__ void prep_w(const float* __restrict__ W1, const float* __restrict__ W2) {
    __shared__ float tile[32][33];
    int bx = blockIdx.x;
    int tx = threadIdx.x & 31, ty = threadIdx.x >> 5;   // 32 x 8
    if (bx < 544) {
        int k0 = (bx % 17) * 32, n0 = (bx / 17) * 32;
#pragma unroll
        for (int i = 0; i < 4; ++i)
            tile[ty + 8 * i][tx] = W1[(size_t)(k0 + ty + 8 * i) * HIDDEN + n0 + tx];
        __syncthreads();
#pragma unroll
        for (int i = 0; i < 4; ++i)
            g_B1[(size_t)(n0 + ty + 8 * i) * K1PAD + k0 + tx] =
                __float2half_rn(tile[tx][ty + 8 * i]);
    } else {
        int b2 = bx - 544;
        int k0 = (b2 % 32) * 32, n0 = (b2 / 32) * 32;
#pragma unroll
        for (int i = 0; i < 4; ++i)
            tile[ty + 8 * i][tx] = W2[(size_t)(k0 + ty + 8 * i) * NODE_F + n0 + tx];
        __syncthreads();
#pragma unroll
        for (int i = 0; i < 4; ++i)
            g_B2[(size_t)(n0 + ty + 8 * i) * HIDDEN + k0 + tx] =
                __float2half_rn(tile[tx][ty + 8 * i]);
    }
}

// ---------------- phase 2: warp-mma fp16 GEMM --------------------------------
// CTA tile 128x256, BK=32. 512 threads, 16 warps in 4(m) x 4(n); warp 32x64.
// SMEM stage: A(8KB) B(16KB) = 24KB; 3 stages = 72KB.
#define STAGE_B 24576

__device__ __forceinline__ void issue_stage(
    uint32_t smemS, const __half* __restrict__ A, const __half* __restrict__ B,
    int mBase, int cBase, int Kpad, int k0, int tid)
{
#pragma unroll
    for (int j = 0; j < 3; ++j) {
        int t = tid + 512 * j;                  // 0..1535
        if (t < 512) {                          // A: 128 rows x 4 chunks
            int row = t >> 2, ch = t & 3;
            uint32_t dst = smemS + row * 64 + ((ch ^ (row & 3)) << 4);
            CPASYNC16(dst, A + (size_t)(mBase + row) * Kpad + k0 + ch * 8);
        } else {                                // B: 256 rows x 4 chunks
            int idx = t - 512;
            int row = idx >> 2, ch = idx & 3;
            uint32_t dst = smemS + 8192 + row * 64 + ((ch ^ (row & 3)) << 4);
            CPASYNC16(dst, B + (size_t)(cBase + row) * Kpad + k0 + ch * 8);
        }
    }
}

template<int EPI>
__global__ __launch_bounds__(512, 1)
void mma_gemm(const __half* __restrict__ A, const __half* __restrict__ B,
              const float* __restrict__ bias, const float* __restrict__ resid,
              const int* __restrict__ batchArr, const float* __restrict__ ubT,
              __half* __restrict__ Oh, float* __restrict__ outF, int Kpad, int ldo)
{
    extern __shared__ char smem[];
    const uint32_t sb = smem_u32(smem);
    const int tid = threadIdx.x;
    const int wid = tid >> 5, lid = tid & 31;
    const int wm = wid >> 2, wn = wid & 3;          // 4x4 warp grid

    const int mBase = blockIdx.y * 128;
    const int cBase = blockIdx.x * 256;
    const int NC = Kpad >> 5;

    const int aRow = wm * 32 + ((lid >> 3) & 1) * 8 + (lid & 7);
    const int aK   = (lid >> 4) & 1;
    const int aB   = aRow * 64, aM = aRow & 3;
    const int bRow = wn * 64 + ((lid >> 4) & 1) * 8 + (lid & 7);
    const int bK   = (lid >> 3) & 1;
    const int bB   = bRow * 64, bM = bRow & 3;

    float acc[2][8][4];
#pragma unroll
    for (int m = 0; m < 2; ++m)
#pragma unroll
        for (int n = 0; n < 8; ++n)
#pragma unroll
            for (int c = 0; c < 4; ++c) acc[m][n][c] = 0.f;

    issue_stage(sb,           A, B, mBase, cBase, Kpad, 0,  tid); CPCOMMIT();
    issue_stage(sb + STAGE_B, A, B, mBase, cBase, Kpad, 32, tid); CPCOMMIT();

    for (int i = 0; i < NC; ++i) {
        if (i + 2 < NC)
            issue_stage(sb + ((i + 2) % 3) * STAGE_B, A, B,
                        mBase, cBase, Kpad, (i + 2) * 32, tid);
        CPCOMMIT();
        CPWAIT2();
        __syncthreads();

        const uint32_t S = sb + (i % 3) * STAGE_B;
#pragma unroll
        for (int ks = 0; ks < 2; ++ks) {
            uint32_t ah[2][4], bh[4][4];
            const int kcA = ks * 2 + aK;
            const uint32_t offA = ((kcA ^ aM) << 4) + aB;
#pragma unroll
            for (int ms = 0; ms < 2; ++ms)
                LDSM4(ah[ms][0], ah[ms][1], ah[ms][2], ah[ms][3], S + offA + ms * 1024);
            const int kcB = ks * 2 + bK;
            const uint32_t offB = ((kcB ^ bM) << 4) + bB;
#pragma unroll
            for (int nb = 0; nb < 4; ++nb)
                LDSM4(bh[nb][0], bh[nb][1], bh[nb][2], bh[nb][3], S + 8192 + offB + nb * 1024);
#pragma unroll
            for (int ms = 0; ms < 2; ++ms)
#pragma unroll
                for (int ns = 0; ns < 8; ++ns) {
                    const int nb = ns >> 1, h = (ns & 1) * 2;
                    MMA16816(acc[ms][ns], ah[ms], bh[nb][h], bh[nb][h + 1]);
                }
        }
        __syncthreads();
    }

    // ---------------- epilogue ----------------
    const int l4 = lid >> 2, l2 = (lid & 3) * 2;
#pragma unroll
    for (int ms = 0; ms < 2; ++ms) {
        const int r0 = mBase + wm * 32 + ms * 16 + l4;
        const int r1 = r0 + 8;
        const float* ub0 = nullptr;
        const float* ub1 = nullptr;
        if (EPI == 1) {
            int g0 = (r0 < N_NODES) ? __ldg(&batchArr[r0]) : 0;
            int g1 = (r1 < N_NODES) ? __ldg(&batchArr[r1]) : 0;
            ub0 = ubT + (size_t)g0 * HIDDEN;
            ub1 = ubT + (size_t)g1 * HIDDEN;
        }
#pragma unroll
        for (int ns = 0; ns < 8; ++ns) {
            const int col = cBase + wn * 64 + ns * 8 + l2;
            if (EPI == 1) {
                float v00 = fmaxf(acc[ms][ns][0] + __ldg(&ub0[col]),     0.f);
                float v01 = fmaxf(acc[ms][ns][1] + __ldg(&ub0[col + 1]), 0.f);
                float v10 = fmaxf(acc[ms][ns][2] + __ldg(&ub1[col]),     0.f);
                float v11 = fmaxf(acc[ms][ns][3] + __ldg(&ub1[col + 1]), 0.f);
                *(uint32_t*)(Oh + (size_t)r0 * ldo + col) = pk_h(v00, v01);
                *(uint32_t*)(Oh + (size_t)r1 * ldo + col) = pk_h(v10, v11);
            } else {
                const float b0 = __ldg(&bias[col]), b1v = __ldg(&bias[col + 1]);
                if (r0 < N_NODES) {
                    const float* xr = resid + (size_t)r0 * NODE_F + col;
                    *(float2*)(outF + (size_t)r0 * ldo + col) =
                        make_float2(acc[ms][ns][0] + b0 + xr[0],
                                    acc[ms][ns][1] + b1v + xr[1]);
                }
                if (r1 < N_NODES) {
                    const float* xr = resid + (size_t)r1 * NODE_F + col;
                    *(float2*)(outF + (size_t)r1 * ldo + col) =
                        make_float2(acc[ms][ns][2] + b0 + xr[0],
                                    acc[ms][ns][3] + b1v + xr[1]);
                }
            }
        }
    }
}

// ---------------------------------------------------------------------------
extern "C" void kernel_launch(void* const* d_in, const int* in_sizes, int n_in,
                              void* d_out, int out_size) {
    const float* x     = (const float*)d_in[0];
    const float* ea    = (const float*)d_in[1];
    const float* u     = (const float*)d_in[2];
    const float* W1    = (const float*)d_in[3];
    const float* b1    = (const float*)d_in[4];
    const float* W2    = (const float*)d_in[5];
    const float* b2    = (const float*)d_in[6];
    const int*   ei    = (const int*)  d_in[7];   // [2, N_EDGES]; row 1 = dst
    const int*   batch = (const int*)  d_in[8];
    float*       out   = (float*)d_out;
    const int*   dst   = ei + N_EDGES;

    __half *A, *H, *B1, *B2;
    float* ubT;
    cudaGetSymbolAddress((void**)&A,  g_A);
    cudaGetSymbolAddress((void**)&H,  g_H);
    cudaGetSymbolAddress((void**)&B1, g_B1);
    cudaGetSymbolAddress((void**)&B2, g_B2);
    cudaGetSymbolAddress((void**)&ubT, g_ub);

    const int SMEM_SZ = 3 * STAGE_B;
    cudaFuncSetAttribute(mma_gemm<1>, cudaFuncAttributeMaxDynamicSharedMemorySize, SMEM_SZ);
    cudaFuncSetAttribute(mma_gemm<2>, cudaFuncAttributeMaxDynamicSharedMemorySize, SMEM_SZ);

    // Fork: weight-prep branch runs on s1 while the CSR chain runs on main.
    cudaStream_t s1;
    cudaStreamCreateWithFlags(&s1, cudaStreamNonBlocking);
    cudaEvent_t evFork, evJoin;
    cudaEventCreateWithFlags(&evFork, cudaEventDisableTiming);
    cudaEventCreateWithFlags(&evJoin, cudaEventDisableTiming);

    cudaEventRecord(evFork, 0);
    cudaStreamWaitEvent(s1, evFork, 0);
    ub_kernel<<<(N_GRAPHS * HIDDEN + 255) / 256, 256, 0, s1>>>(u, W1, b1);
    prep_w<<<544 + 256, 256, 0, s1>>>(W1, W2);
    pad_rows<<<((MPAD - N_NODES) * 136 + 255) / 256, 256, 0, s1>>>();
    cudaEventRecord(evJoin, s1);

    // CSR build + fused gather/compose (main stream)
    zero_counts<<<(N_NODES + 255) / 256, 256>>>();
    count_kernel<<<(N_EDGES + 255) / 256, 256>>>(dst);
    scan_kernel<<<1, 1024>>>();
    fill_kernel<<<(N_EDGES + 255) / 256, 256>>>(dst);
    gather_kernel<<<(N_NODES * 32 + 255) / 256, 256>>>(ea, x);

    cudaStreamWaitEvent(0, evJoin, 0);

    mma_gemm<1><<<dim3(HIDDEN / 256, MTILES), 512, SMEM_SZ>>>(
        A, B1, nullptr, nullptr, batch, ubT, H, nullptr, K1PAD, HIDDEN);
    mma_gemm<2><<<dim3(1, MTILES), 512, SMEM_SZ>>>(
        H, B2, b2, x, nullptr, nullptr, nullptr, out, HIDDEN, NODE_F);

    cudaEventDestroy(evFork);
    cudaEventDestroy(evJoin);
    cudaStreamDestroy(s1);
}

// round 15
// speedup vs baseline: 1.1214x; 1.1214x over previous
#include <cuda_runtime.h>
#include <cuda_fp16.h>
#include <cstdint>

#define N_NODES 50000
#define N_EDGES 800000
#define EDGE_F  96
#define NODE_F  256
#define GLOB_F  64
#define HIDDEN  1024
#define N_GRAPHS 8
#define K1PAD   544              // x|sum|max|mean = 544 = 17*32
#define MTILES  391
#define MPAD    (MTILES*128)     // 50048

// ---------------- device scratch (allocation-free per harness rules) -------
__device__ int   g_cnt[N_NODES];                   // counts, then fill-cursor
__device__ int   g_start[N_NODES + 1];             // CSR offsets (+sentinel)
__device__ int   g_eidx[N_EDGES];
__device__ float g_ub[N_GRAPHS * HIDDEN];          // b1 + u[g] @ W1u
__device__ __half g_A [(size_t)MPAD*K1PAD];        // fp16 MLP input
__device__ __half g_H [(size_t)MPAD*HIDDEN];       // fp16 hidden acts
__device__ __half g_B1[(size_t)HIDDEN*K1PAD];      // W1^T fp16
__device__ __half g_B2[(size_t)NODE_F*HIDDEN];     // W2^T fp16

// ---------------- PTX helpers ----------------------------------------------
__device__ __forceinline__ uint32_t smem_u32(const void* p) {
    uint32_t a;
    asm("{ .reg .u64 t; cvta.to.shared.u64 t, %1; cvt.u32.u64 %0, t; }" : "=r"(a) : "l"(p));
    return a;
}
#define CPASYNC16(s,g) asm volatile("cp.async.cg.shared.global [%0], [%1], 16;" :: "r"(s), "l"(g))
#define CPCOMMIT()     asm volatile("cp.async.commit_group;" ::: "memory")
#define CPWAIT2()      asm volatile("cp.async.wait_group 2;" ::: "memory")

#define LDSM4(r0,r1,r2,r3,addr) \
    asm volatile("ldmatrix.sync.aligned.m8n8.x4.shared.b16 {%0,%1,%2,%3}, [%4];" \
        : "=r"(r0),"=r"(r1),"=r"(r2),"=r"(r3) : "r"(addr))

#define MMA16816(d,a,b0,b1) \
    asm volatile("mma.sync.aligned.m16n8k16.row.col.f32.f16.f16.f32 " \
        "{%0,%1,%2,%3}, {%4,%5,%6,%7}, {%8,%9}, {%0,%1,%2,%3};" \
        : "+f"((d)[0]),"+f"((d)[1]),"+f"((d)[2]),"+f"((d)[3]) \
        : "r"((a)[0]),"r"((a)[1]),"r"((a)[2]),"r"((a)[3]), "r"(b0),"r"(b1))

__device__ __forceinline__ uint32_t pk_h(float a, float b) {
    __half2 h = __floats2half2_rn(a, b);
    return *(uint32_t*)&h;
}

// ---------------- phase 1: CSR build + fused gather/compose ------------------
__global__ void zero_counts() {
    int i = blockIdx.x * blockDim.x + threadIdx.x;
    if (i < N_NODES) g_cnt[i] = 0;
}
__global__ void count_kernel(const int* __restrict__ dst) {
    int i = blockIdx.x * blockDim.x + threadIdx.x;
    if (i < N_EDGES) atomicAdd(&g_cnt[dst[i]], 1);
}
// single block, 1024 threads; warp-shuffle scan
__global__ void scan_kernel() {
    __shared__ int wsum[32];
    __shared__ int carry;
    int tid = threadIdx.x;
    int lane = tid & 31, warp = tid >> 5;
    if (tid == 0) carry = 0;
    __syncthreads();
    for (int base = 0; base < N_NODES; base += 1024) {
        int i = base + tid;
        int v = (i < N_NODES) ? g_cnt[i] : 0;
        int inc = v;
#pragma unroll
        for (int off = 1; off < 32; off <<= 1) {
            int t = __shfl_up_sync(0xffffffff, inc, off);
            if (lane >= off) inc += t;
        }
        if (lane == 31) wsum[warp] = inc;
        __syncthreads();
        if (warp == 0) {
            int w = wsum[lane];
#pragma unroll
            for (int off = 1; off < 32; off <<= 1) {
                int t = __shfl_up_sync(0xffffffff, w, off);
                if (lane >= off) w += t;
            }
            wsum[lane] = w;
        }
        __syncthreads();
        int excl = inc - v + (warp > 0 ? wsum[warp - 1] : 0) + carry;
        if (i < N_NODES) {
            g_start[i] = excl;
            g_cnt[i] = 0;                       // reset: becomes fill cursor
        }
        __syncthreads();
        if (tid == 1023) carry = excl + v;
        __syncthreads();
    }
    if (tid == 0) g_start[N_NODES] = N_EDGES;   // sentinel
}
__global__ void fill_kernel(const int* __restrict__ dst) {
    int i = blockIdx.x * blockDim.x + threadIdx.x;
    if (i >= N_EDGES) return;
    int c = dst[i];
    int p = atomicAdd(&g_cnt[c], 1);
    g_eidx[g_start[c] + p] = i;
}
// warp per node; lanes 0-23 own float4 feature chunks {4l..4l+3}.
// Unrolled x4 -> up to 96 independent 16B loads in flight per warp.
__global__ void gather_kernel(const float* __restrict__ ea, const float* __restrict__ x) {
    int w = (blockIdx.x * blockDim.x + threadIdx.x) >> 5;
    int lid = threadIdx.x & 31;
    if (w >= N_NODES) return;
    int s = g_start[w], d = g_start[w + 1] - s;
    float ninf = __int_as_float(0xff800000);
    float4 sum = make_float4(0.f, 0.f, 0.f, 0.f);
    float4 mx  = make_float4(ninf, ninf, ninf, ninf);
    if (lid < 24) {
        int j = 0;
        for (; j + 4 <= d; j += 4) {
            const float4* r0 = (const float4*)(ea + (size_t)g_eidx[s + j]     * EDGE_F) + lid;
            const float4* r1 = (const float4*)(ea + (size_t)g_eidx[s + j + 1] * EDGE_F) + lid;
            const float4* r2 = (const float4*)(ea + (size_t)g_eidx[s + j + 2] * EDGE_F) + lid;
            const float4* r3 = (const float4*)(ea + (size_t)g_eidx[s + j + 3] * EDGE_F) + lid;
            float4 a = *r0, b = *r1, c = *r2, e = *r3;
            sum.x += a.x + b.x + c.x + e.x;
            sum.y += a.y + b.y + c.y + e.y;
            sum.z += a.z + b.z + c.z + e.z;
            sum.w += a.w + b.w + c.w + e.w;
            mx.x = fmaxf(fmaxf(fmaxf(mx.x, a.x), fmaxf(b.x, c.x)), e.x);
            mx.y = fmaxf(fmaxf(fmaxf(mx.y, a.y), fmaxf(b.y, c.y)), e.y);
            mx.z = fmaxf(fmaxf(fmaxf(mx.z, a.z), fmaxf(b.z, c.z)), e.z);
            mx.w = fmaxf(fmaxf(fmaxf(mx.w, a.w), fmaxf(b.w, c.w)), e.w);
        }
        for (; j < d; ++j) {
            float4 a = *((const float4*)(ea + (size_t)g_eidx[s + j] * EDGE_F) + lid);
            sum.x += a.x; sum.y += a.y; sum.z += a.z; sum.w += a.w;
            mx.x = fmaxf(mx.x, a.x); mx.y = fmaxf(mx.y, a.y);
            mx.z = fmaxf(mx.z, a.z); mx.w = fmaxf(mx.w, a.w);
        }
    }
    if (d == 0) mx = make_float4(0.f, 0.f, 0.f, 0.f);
    float inv = d > 0 ? 1.f / (float)d : 0.f;

    __half* A = g_A + (size_t)w * K1PAD;
    if (lid < 24) {
        int c0 = 4 * lid;
        *(uint2*)(A + 256 + c0) = make_uint2(pk_h(sum.x, sum.y), pk_h(sum.z, sum.w));
        *(uint2*)(A + 352 + c0) = make_uint2(pk_h(mx.x, mx.y),  pk_h(mx.z, mx.w));
        *(uint2*)(A + 448 + c0) = make_uint2(pk_h(sum.x * inv, sum.y * inv),
                                             pk_h(sum.z * inv, sum.w * inv));
    }
    const float4* xr = (const float4*)(x + (size_t)w * NODE_F);
#pragma unroll
    for (int t = 0; t < 2; ++t) {
        int c4 = t * 32 + lid;                  // float4 index 0..63
        float4 v = xr[c4];
        *(uint2*)(A + 4 * c4) = make_uint2(pk_h(v.x, v.y), pk_h(v.z, v.w));
    }
}
// zero the padding rows [N_NODES, MPAD)
__global__ void pad_rows() {
    int i = blockIdx.x * blockDim.x + threadIdx.x;   // (MPAD-N_NODES)*136 uint2
    if (i >= (MPAD - N_NODES) * 136) return;
    int n = N_NODES + i / 136, q = i - (i / 136) * 136;
    *(uint2*)(g_A + (size_t)n * K1PAD + 4 * q) = make_uint2(0u, 0u);
}

// u-bias table: ub[g][n] = b1[n] + sum_k u[g][k] * W1[544+k][n]
__global__ void ub_kernel(const float* __restrict__ u, const float* __restrict__ W1,
                          const float* __restrict__ b1) {
    int i = blockIdx.x * blockDim.x + threadIdx.x;
    if (i >= N_GRAPHS * HIDDEN) return;
    int g = i / HIDDEN, n = i - g * HIDDEN;
    float acc = b1[n];
#pragma unroll 8
    for (int k = 0; k < GLOB_F; ++k)
        acc += u[(size_t)g * GLOB_F + k] * W1[(size_t)(544 + k) * HIDDEN + n];
    g_ub[i] = acc;
}

// coalesced 32x32 smem-tile transpose + fp16 convert of W1 (k<544) and W2.
__global__ void prep_w(const float* __restrict__ W1, const float* __restrict__ W2) {
    __shared__ float tile[32][33];
    int bx = blockIdx.x;
    int tx = threadIdx.x & 31, ty = threadIdx.x >> 5;   // 32 x 8
    if (bx < 544) {
        int k0 = (bx % 17) * 32, n0 = (bx / 17) * 32;
#pragma unroll
        for (int i = 0; i < 4; ++i)
            tile[ty + 8 * i][tx] = W1[(size_t)(k0 + ty + 8 * i) * HIDDEN + n0 + tx];
        __syncthreads();
#pragma unroll
        for (int i = 0; i < 4; ++i)
            g_B1[(size_t)(n0 + ty + 8 * i) * K1PAD + k0 + tx] =
                __float2half_rn(tile[tx][ty + 8 * i]);
    } else {
        int b2 = bx - 544;
        int k0 = (b2 % 32) * 32, n0 = (b2 / 32) * 32;
#pragma unroll
        for (int i = 0; i < 4; ++i)
            tile[ty + 8 * i][tx] = W2[(size_t)(k0 + ty + 8 * i) * NODE_F + n0 + tx];
        __syncthreads();
#pragma unroll
        for (int i = 0; i < 4; ++i)
            g_B2[(size_t)(n0 + ty + 8 * i) * HIDDEN + k0 + tx] =
                __float2half_rn(tile[tx][ty + 8 * i]);
    }
}

// ---------------- phase 2: warp-mma fp16 GEMM --------------------------------
// CTA tile 128x128, BK=32. 8 warps 4(m) x 2(n); warp tile 32x64.
// SMEM stage: A(8KB) B(8KB) = 16KB; 3 stages = 48KB.
#define STAGE_B 16384

__device__ __forceinline__ void issue_stage(
    uint32_t smemS, const __half* __restrict__ A, const __half* __restrict__ B,
    int mBase, int cBase, int Kpad, int k0, int tid)
{
#pragma unroll
    for (int j = 0; j < 4; ++j) {
        int t4  = tid + 256 * j;
        int tile = t4 >> 9;
        int idx  = t4 & 511;
        int row  = idx >> 2;
        int ch   = idx & 3;
        uint32_t dst = smemS + tile * 8192 + row * 64 + ((ch ^ (row & 3)) << 4);
        const __half* src = (tile == 0)
            ? A + (size_t)(mBase + row) * Kpad + k0 + ch * 8
            : B + (size_t)(cBase + row) * Kpad + k0 + ch * 8;
        CPASYNC16(dst, src);
    }
}

template<int EPI>
__global__ __launch_bounds__(256, 2)
void mma_gemm(const __half* __restrict__ A, const __half* __restrict__ B,
              const float* __restrict__ bias, const float* __restrict__ resid,
              const int* __restrict__ batchArr, const float* __restrict__ ubT,
              __half* __restrict__ Oh, float* __restrict__ outF, int Kpad, int ldo)
{
    extern __shared__ char smem[];
    const uint32_t sb = smem_u32(smem);
    const int tid = threadIdx.x;
    const int wid = tid >> 5, lid = tid & 31;
    const int wm = wid >> 1, wn = wid & 1;          // 4x2 warp grid

    const int mBase = blockIdx.y * 128;
    const int cBase = blockIdx.x * 128;
    const int NC = Kpad >> 5;

    const int aRow = wm * 32 + ((lid >> 3) & 1) * 8 + (lid & 7);
    const int aK   = (lid >> 4) & 1;
    const int aB   = aRow * 64, aM = aRow & 3;
    const int bRow = wn * 64 + ((lid >> 4) & 1) * 8 + (lid & 7);
    const int bK   = (lid >> 3) & 1;
    const int bB   = bRow * 64, bM = bRow & 3;

    float acc[2][8][4];
#pragma unroll
    for (int m = 0; m < 2; ++m)
#pragma unroll
        for (int n = 0; n < 8; ++n)
#pragma unroll
            for (int c = 0; c < 4; ++c) acc[m][n][c] = 0.f;

    issue_stage(sb,           A, B, mBase, cBase, Kpad, 0,  tid); CPCOMMIT();
    issue_stage(sb + STAGE_B, A, B, mBase, cBase, Kpad, 32, tid); CPCOMMIT();

    for (int i = 0; i < NC; ++i) {
        if (i + 2 < NC)
            issue_stage(sb + ((i + 2) % 3) * STAGE_B, A, B,
                        mBase, cBase, Kpad, (i + 2) * 32, tid);
        CPCOMMIT();
        CPWAIT2();
        __syncthreads();

        const uint32_t S = sb + (i % 3) * STAGE_B;
#pragma unroll
        for (int ks = 0; ks < 2; ++ks) {
            uint32_t ah[2][4], bh[4][4];
            const int kcA = ks * 2 + aK;
            const uint32_t offA = ((kcA ^ aM) << 4) + aB;
#pragma unroll
            for (int ms = 0; ms < 2; ++ms)
                LDSM4(ah[ms][0], ah[ms][1], ah[ms][2], ah[ms][3], S + offA + ms * 1024);
            const int kcB = ks * 2 + bK;
            const uint32_t offB = ((kcB ^ bM) << 4) + bB;
#pragma unroll
            for (int nb = 0; nb < 4; ++nb)
                LDSM4(bh[nb][0], bh[nb][1], bh[nb][2], bh[nb][3], S + 8192 + offB + nb * 1024);
#pragma unroll
            for (int ms = 0; ms < 2; ++ms)
#pragma unroll
                for (int ns = 0; ns < 8; ++ns) {
                    const int nb = ns >> 1, h = (ns & 1) * 2;
                    MMA16816(acc[ms][ns], ah[ms], bh[nb][h], bh[nb][h + 1]);
                }
        }
        __syncthreads();
    }

    // ---------------- epilogue ----------------
    const int l4 = lid >> 2, l2 = (lid & 3) * 2;
#pragma unroll
    for (int ms = 0; ms < 2; ++ms) {
        const int r0 = mBase + wm * 32 + ms * 16 + l4;
        const int r1 = r0 + 8;
        const float* ub0 = nullptr;
        const float* ub1 = nullptr;
        if (EPI == 1) {
            int g0 = (r0 < N_NODES) ? __ldg(&batchArr[r0]) : 0;
            int g1 = (r1 < N_NODES) ? __ldg(&batchArr[r1]) : 0;
            ub0 = ubT + (size_t)g0 * HIDDEN;
            ub1 = ubT + (size_t)g1 * HIDDEN;
        }
#pragma unroll
        for (int ns = 0; ns < 8; ++ns) {
            const int col = cBase + wn * 64 + ns * 8 + l2;
            if (EPI == 1) {
                float v00 = fmaxf(acc[ms][ns][0] + __ldg(&ub0[col]),     0.f);
                float v01 = fmaxf(acc[ms][ns][1] + __ldg(&ub0[col + 1]), 0.f);
                float v10 = fmaxf(acc[ms][ns][2] + __ldg(&ub1[col]),     0.f);
                float v11 = fmaxf(acc[ms][ns][3] + __ldg(&ub1[col + 1]), 0.f);
                *(uint32_t*)(Oh + (size_t)r0 * ldo + col) = pk_h(v00, v01);
                *(uint32_t*)(Oh + (size_t)r1 * ldo + col) = pk_h(v10, v11);
            } else {
                const float b0 = __ldg(&bias[col]), b1v = __ldg(&bias[col + 1]);
                if (r0 < N_NODES) {
                    const float* xr = resid + (size_t)r0 * NODE_F + col;
                    *(float2*)(outF + (size_t)r0 * ldo + col) =
                        make_float2(acc[ms][ns][0] + b0 + xr[0],
                                    acc[ms][ns][1] + b1v + xr[1]);
                }
                if (r1 < N_NODES) {
                    const float* xr = resid + (size_t)r1 * NODE_F + col;
                    *(float2*)(outF + (size_t)r1 * ldo + col) =
                        make_float2(acc[ms][ns][2] + b0 + xr[0],
                                    acc[ms][ns][3] + b1v + xr[1]);
                }
            }
        }
    }
}

// ---------------------------------------------------------------------------
extern "C" void kernel_launch(void* const* d_in, const int* in_sizes, int n_in,
                              void* d_out, int out_size) {
    const float* x     = (const float*)d_in[0];
    const float* ea    = (const float*)d_in[1];
    const float* u     = (const float*)d_in[2];
    const float* W1    = (const float*)d_in[3];
    const float* b1    = (const float*)d_in[4];
    const float* W2    = (const float*)d_in[5];
    const float* b2    = (const float*)d_in[6];
    const int*   ei    = (const int*)  d_in[7];   // [2, N_EDGES]; row 1 = dst
    const int*   batch = (const int*)  d_in[8];
    float*       out   = (float*)d_out;
    const int*   dst   = ei + N_EDGES;

    __half *A, *H, *B1, *B2;
    float* ubT;
    cudaGetSymbolAddress((void**)&A,  g_A);
    cudaGetSymbolAddress((void**)&H,  g_H);
    cudaGetSymbolAddress((void**)&B1, g_B1);
    cudaGetSymbolAddress((void**)&B2, g_B2);
    cudaGetSymbolAddress((void**)&ubT, g_ub);

    const int SMEM_SZ = 3 * STAGE_B;
    cudaFuncSetAttribute(mma_gemm<1>, cudaFuncAttributeMaxDynamicSharedMemorySize, SMEM_SZ);
    cudaFuncSetAttribute(mma_gemm<2>, cudaFuncAttributeMaxDynamicSharedMemorySize, SMEM_SZ);

    // Fork: weight-prep branch runs on s1 while the CSR chain runs on main.
    cudaStream_t s1;
    cudaStreamCreateWithFlags(&s1, cudaStreamNonBlocking);
    cudaEvent_t evFork, evJoin;
    cudaEventCreateWithFlags(&evFork, cudaEventDisableTiming);
    cudaEventCreateWithFlags(&evJoin, cudaEventDisableTiming);

    cudaEventRecord(evFork, 0);
    cudaStreamWaitEvent(s1, evFork, 0);
    ub_kernel<<<(N_GRAPHS * HIDDEN + 255) / 256, 256, 0, s1>>>(u, W1, b1);
    prep_w<<<544 + 256, 256, 0, s1>>>(W1, W2);
    pad_rows<<<((MPAD - N_NODES) * 136 + 255) / 256, 256, 0, s1>>>();
    cudaEventRecord(evJoin, s1);

    // CSR build + fused gather/compose (main stream)
    zero_counts<<<(N_NODES + 255) / 256, 256>>>();
    count_kernel<<<(N_EDGES + 255) / 256, 256>>>(dst);
    scan_kernel<<<1, 1024>>>();
    fill_kernel<<<(N_EDGES + 255) / 256, 256>>>(dst);
    gather_kernel<<<(N_NODES * 32 + 255) / 256, 256>>>(ea, x);

    cudaStreamWaitEvent(0, evJoin, 0);

    mma_gemm<1><<<dim3(HIDDEN / 128, MTILES), 256, SMEM_SZ>>>(
        A, B1, nullptr, nullptr, batch, ubT, H, nullptr, K1PAD, HIDDEN);
    mma_gemm<2><<<dim3(NODE_F / 128, MTILES), 256, SMEM_SZ>>>(
        H, B2, b2, x, nullptr, nullptr, nullptr, out, HIDDEN, NODE_F);

    cudaEventDestroy(evFork);
    cudaEventDestroy(evJoin);
    cudaStreamDestroy(s1);
}